// round 1
// baseline (speedup 1.0000x reference)
#include <cuda_runtime.h>

#define BB 4
#define TT 2048
#define HH 12
#define DD 64
#define CC 768
#define MM (BB*TT)

// Scratch (alloc-free rule: __device__ globals)
__device__ float g_q[MM*CC];
__device__ float g_k[MM*CC];
__device__ float g_v[MM*CC];
__device__ float g_o[MM*CC];

// ---------------------------------------------------------------------------
// SGEMM: C[M,N] = A[M,K] * B[N,K]^T   (both row-major, K contiguous)
// Block tile 64x64, K-tile 16, 256 threads, 4x4 register micro-tile.
// ---------------------------------------------------------------------------
__global__ __launch_bounds__(256) void sgemm_nt(const float* __restrict__ A,
                                                const float* __restrict__ B,
                                                float* __restrict__ C,
                                                int M, int N, int K) {
    __shared__ float As[16][64];
    __shared__ float Bs[16][64];

    const int tid = threadIdx.x;
    const int tx = tid & 15;        // 0..15 -> cols
    const int ty = tid >> 4;        // 0..15 -> rows
    const int row0 = blockIdx.y * 64;
    const int col0 = blockIdx.x * 64;

    const int lr = tid >> 2;        // 0..63 tile row for loading
    const int lk = (tid & 3) << 2;  // 0,4,8,12 k-offset for loading

    const float* Ag = A + (size_t)(row0 + lr) * K + lk;
    const float* Bg = B + (size_t)(col0 + lr) * K + lk;

    float acc[4][4] = {};

    for (int k0 = 0; k0 < K; k0 += 16) {
        float4 av = *(const float4*)(Ag + k0);
        float4 bv = *(const float4*)(Bg + k0);
        __syncthreads();  // protect smem from previous iteration's readers
        As[lk + 0][lr] = av.x; As[lk + 1][lr] = av.y;
        As[lk + 2][lr] = av.z; As[lk + 3][lr] = av.w;
        Bs[lk + 0][lr] = bv.x; Bs[lk + 1][lr] = bv.y;
        Bs[lk + 2][lr] = bv.z; Bs[lk + 3][lr] = bv.w;
        __syncthreads();
#pragma unroll
        for (int kk = 0; kk < 16; kk++) {
            float4 a4 = *(const float4*)&As[kk][ty << 2];
            float4 b4 = *(const float4*)&Bs[kk][tx << 2];
            float a[4] = {a4.x, a4.y, a4.z, a4.w};
            float b[4] = {b4.x, b4.y, b4.z, b4.w};
#pragma unroll
            for (int i = 0; i < 4; i++)
#pragma unroll
                for (int j = 0; j < 4; j++)
                    acc[i][j] += a[i] * b[j];
        }
    }

#pragma unroll
    for (int i = 0; i < 4; i++) {
        float4 v = make_float4(acc[i][0], acc[i][1], acc[i][2], acc[i][3]);
        *(float4*)&C[(size_t)(row0 + (ty << 2) + i) * N + col0 + (tx << 2)] = v;
    }
}

// ---------------------------------------------------------------------------
// Causal flash attention. Q,K,V,O all [M, C] row-major; head h = cols
// h*64..h*64+63. One block per (b, h, 64-row q tile). 256 threads.
// Online softmax, 64-key tiles, everything fp32.
// ---------------------------------------------------------------------------
__global__ __launch_bounds__(256) void attn_kernel(const float* __restrict__ Q,
                                                   const float* __restrict__ K,
                                                   const float* __restrict__ V,
                                                   float* __restrict__ O) {
    extern __shared__ float sm[];
    float* Qt = sm;              // [64 d][64 r]   transposed
    float* Kt = sm + 4096;       // [64 d][64 c]   transposed
    float* Vs = sm + 8192;       // [64 c][64 d]   natural
    float* Ps = sm + 12288;      // [64 c][65]     transposed, padded stride

    const int tid = threadIdx.x;
    const int tx = tid & 15;
    const int ty = tid >> 4;
    const int bh = blockIdx.y;
    const int b  = bh / HH;
    const int h  = bh - b * HH;
    const int qt = (int)gridDim.x - 1 - (int)blockIdx.x;  // heavy tiles first
    const int q0 = qt * 64;

    const int lr  = tid >> 2;          // 0..63
    const int dc0 = (tid & 3) << 4;    // 0,16,32,48

    // --- load Q tile, transposed into smem ---
    {
        const float* qg = Q + (size_t)(b * TT + q0 + lr) * CC + h * DD + dc0;
#pragma unroll
        for (int u = 0; u < 4; u++) {
            float4 v = *(const float4*)(qg + 4 * u);
            int d = dc0 + 4 * u;
            Qt[(d + 0) * 64 + lr] = v.x;
            Qt[(d + 1) * 64 + lr] = v.y;
            Qt[(d + 2) * 64 + lr] = v.z;
            Qt[(d + 3) * 64 + lr] = v.w;
        }
    }

    float m_run[4], l_run[4], o_acc[4][4];
#pragma unroll
    for (int i = 0; i < 4; i++) {
        m_run[i] = -1e30f;
        l_run[i] = 0.0f;
#pragma unroll
        for (int j = 0; j < 4; j++) o_acc[i][j] = 0.0f;
    }

    const int r0 = ty << 2;
    const int c0 = tx << 2;

    for (int kt = 0; kt <= qt; kt++) {
        const int k0 = kt * 64;
        __syncthreads();  // previous iteration done with Kt/Vs/Ps
        // --- load K (transposed) and V (natural) tiles ---
        {
            const float* kg = K + (size_t)(b * TT + k0 + lr) * CC + h * DD + dc0;
            const float* vg = V + (size_t)(b * TT + k0 + lr) * CC + h * DD + dc0;
#pragma unroll
            for (int u = 0; u < 4; u++) {
                float4 kv = *(const float4*)(kg + 4 * u);
                float4 vv = *(const float4*)(vg + 4 * u);
                int d = dc0 + 4 * u;
                Kt[(d + 0) * 64 + lr] = kv.x;
                Kt[(d + 1) * 64 + lr] = kv.y;
                Kt[(d + 2) * 64 + lr] = kv.z;
                Kt[(d + 3) * 64 + lr] = kv.w;
                *(float4*)&Vs[lr * 64 + d] = vv;
            }
        }
        __syncthreads();

        // --- S = Q K^T (4x4 per thread) ---
        float s[4][4] = {};
#pragma unroll 8
        for (int d = 0; d < 64; d++) {
            float4 a4 = *(const float4*)&Qt[d * 64 + r0];
            float4 b4 = *(const float4*)&Kt[d * 64 + c0];
            float a[4] = {a4.x, a4.y, a4.z, a4.w};
            float bq[4] = {b4.x, b4.y, b4.z, b4.w};
#pragma unroll
            for (int i = 0; i < 4; i++)
#pragma unroll
                for (int j = 0; j < 4; j++)
                    s[i][j] += a[i] * bq[j];
        }

        // --- scale + causal mask (only diagonal tile can mask) ---
        const bool diag = (kt == qt);
#pragma unroll
        for (int i = 0; i < 4; i++)
#pragma unroll
            for (int j = 0; j < 4; j++) {
                float v = s[i][j] * 0.125f;  // D^-0.5 = 1/8
                if (diag && (c0 + j > r0 + i)) v = -1e30f;
                s[i][j] = v;
            }

        // --- online softmax (row reductions across the 16 tx lanes) ---
        float m_new[4], alpha[4];
#pragma unroll
        for (int i = 0; i < 4; i++) {
            float mx = fmaxf(fmaxf(s[i][0], s[i][1]), fmaxf(s[i][2], s[i][3]));
#pragma unroll
            for (int m = 8; m >= 1; m >>= 1)
                mx = fmaxf(mx, __shfl_xor_sync(0xffffffffu, mx, m));
            m_new[i] = fmaxf(m_run[i], mx);
            alpha[i] = __expf(m_run[i] - m_new[i]);
            m_run[i] = m_new[i];
        }
#pragma unroll
        for (int i = 0; i < 4; i++) {
            float ls = 0.0f;
#pragma unroll
            for (int j = 0; j < 4; j++) {
                s[i][j] = __expf(s[i][j] - m_new[i]);
                ls += s[i][j];
            }
#pragma unroll
            for (int m = 8; m >= 1; m >>= 1)
                ls += __shfl_xor_sync(0xffffffffu, ls, m);
            l_run[i] = l_run[i] * alpha[i] + ls;
#pragma unroll
            for (int j = 0; j < 4; j++) o_acc[i][j] *= alpha[i];
        }

        // --- write P transposed to smem (stride 65) ---
#pragma unroll
        for (int i = 0; i < 4; i++)
#pragma unroll
            for (int j = 0; j < 4; j++)
                Ps[(c0 + j) * 65 + r0 + i] = s[i][j];
        __syncthreads();

        // --- O += P V ---
#pragma unroll 8
        for (int c = 0; c < 64; c++) {
            float a0 = Ps[c * 65 + r0 + 0];
            float a1 = Ps[c * 65 + r0 + 1];
            float a2 = Ps[c * 65 + r0 + 2];
            float a3 = Ps[c * 65 + r0 + 3];
            float4 b4 = *(const float4*)&Vs[c * 64 + c0];
            float bq[4] = {b4.x, b4.y, b4.z, b4.w};
            float a[4] = {a0, a1, a2, a3};
#pragma unroll
            for (int i = 0; i < 4; i++)
#pragma unroll
                for (int j = 0; j < 4; j++)
                    o_acc[i][j] += a[i] * bq[j];
        }
    }

    // --- normalize + write O tile ---
#pragma unroll
    for (int i = 0; i < 4; i++) {
        float inv = 1.0f / l_run[i];
        float4 v = make_float4(o_acc[i][0] * inv, o_acc[i][1] * inv,
                               o_acc[i][2] * inv, o_acc[i][3] * inv);
        *(float4*)&O[(size_t)(b * TT + q0 + r0 + i) * CC + h * DD + c0] = v;
    }
}

// ---------------------------------------------------------------------------
extern "C" void kernel_launch(void* const* d_in, const int* in_sizes, int n_in,
                              void* d_out, int out_size) {
    const float* x  = (const float*)d_in[0];
    const float* Wq = (const float*)d_in[1];
    const float* Wk = (const float*)d_in[2];
    const float* Wv = (const float*)d_in[3];
    const float* Wp = (const float*)d_in[4];
    float* out = (float*)d_out;

    float *gq, *gk, *gv, *go;
    cudaGetSymbolAddress((void**)&gq, g_q);
    cudaGetSymbolAddress((void**)&gk, g_k);
    cudaGetSymbolAddress((void**)&gv, g_v);
    cudaGetSymbolAddress((void**)&go, g_o);

    const int smem_attn = (4096 * 3 + 64 * 65) * sizeof(float);  // 65792 B
    cudaFuncSetAttribute(attn_kernel,
                         cudaFuncAttributeMaxDynamicSharedMemorySize, smem_attn);

    dim3 gproj(CC / 64, MM / 64);  // (12, 128)
    sgemm_nt<<<gproj, 256>>>(x, Wq, gq, MM, CC, CC);
    sgemm_nt<<<gproj, 256>>>(x, Wk, gk, MM, CC, CC);
    sgemm_nt<<<gproj, 256>>>(x, Wv, gv, MM, CC, CC);

    attn_kernel<<<dim3(TT / 64, BB * HH), 256, smem_attn>>>(gq, gk, gv, go);

    sgemm_nt<<<gproj, 256>>>(go, Wp, out, MM, CC, CC);
}

// round 3
// speedup vs baseline: 3.0322x; 3.0322x over previous
#include <cuda_runtime.h>
#include <cuda_bf16.h>
#include <cstdint>

#define BB 4
#define TT 2048
#define HH 12
#define DD 64
#define CC 768
#define MM (BB*TT)

typedef __nv_bfloat16 bf16;

// ---------------------------------------------------------------------------
// Scratch (__device__ globals; alloc-free rule)
// ---------------------------------------------------------------------------
__device__ bf16 g_xhi[MM*CC], g_xlo[MM*CC];
__device__ bf16 g_whi[4*CC*CC], g_wlo[4*CC*CC];
__device__ bf16 g_qhi[MM*CC], g_qlo[MM*CC];
__device__ bf16 g_khi[MM*CC], g_klo[MM*CC];
__device__ bf16 g_vhi[MM*CC], g_vlo[MM*CC];
__device__ bf16 g_ohi[MM*CC], g_olo[MM*CC];

// ---------------------------------------------------------------------------
// helpers
// ---------------------------------------------------------------------------
__device__ __forceinline__ uint32_t smem_u32(const void* p) {
    uint32_t a;
    asm("{ .reg .u64 t; cvta.to.shared.u64 t, %1; cvt.u32.u64 %0, t; }"
        : "=r"(a) : "l"(p));
    return a;
}
__device__ __forceinline__ void ldsm4(uint32_t* r, uint32_t addr) {
    asm volatile("ldmatrix.sync.aligned.m8n8.x4.shared.b16 {%0,%1,%2,%3}, [%4];\n"
                 : "=r"(r[0]), "=r"(r[1]), "=r"(r[2]), "=r"(r[3]) : "r"(addr));
}
__device__ __forceinline__ void ldsm4t(uint32_t* r, uint32_t addr) {
    asm volatile("ldmatrix.sync.aligned.m8n8.x4.trans.shared.b16 {%0,%1,%2,%3}, [%4];\n"
                 : "=r"(r[0]), "=r"(r[1]), "=r"(r[2]), "=r"(r[3]) : "r"(addr));
}
__device__ __forceinline__ void mma16816(float* c, const uint32_t* a, const uint32_t* b) {
    asm volatile(
        "mma.sync.aligned.m16n8k16.row.col.f32.bf16.bf16.f32 "
        "{%0,%1,%2,%3}, {%4,%5,%6,%7}, {%8,%9}, {%0,%1,%2,%3};\n"
        : "+f"(c[0]), "+f"(c[1]), "+f"(c[2]), "+f"(c[3])
        : "r"(a[0]), "r"(a[1]), "r"(a[2]), "r"(a[3]), "r"(b[0]), "r"(b[1]));
}
__device__ __forceinline__ void cp16(uint32_t dst, const void* src) {
    asm volatile("cp.async.cg.shared.global [%0], [%1], 16;\n" :: "r"(dst), "l"(src));
}
#define CP_COMMIT() asm volatile("cp.async.commit_group;\n")
#define CP_WAIT0()  asm volatile("cp.async.wait_group 0;\n")
#define CP_WAIT1()  asm volatile("cp.async.wait_group 1;\n")

__device__ __forceinline__ void split_pack(float x0, float x1,
                                           uint32_t& phi, uint32_t& plo) {
    bf16 h0 = __float2bfloat16_rn(x0);
    bf16 h1 = __float2bfloat16_rn(x1);
    bf16 l0 = __float2bfloat16_rn(x0 - __bfloat162float(h0));
    bf16 l1 = __float2bfloat16_rn(x1 - __bfloat162float(h1));
    phi = ((uint32_t)__bfloat16_as_ushort(h1) << 16) | __bfloat16_as_ushort(h0);
    plo = ((uint32_t)__bfloat16_as_ushort(l1) << 16) | __bfloat16_as_ushort(l0);
}

// ---------------------------------------------------------------------------
// fp32 -> (bf16 hi, bf16 lo) split
// ---------------------------------------------------------------------------
__global__ void split_fp32(const float* __restrict__ in,
                           bf16* __restrict__ hi, bf16* __restrict__ lo, int n) {
    int i = blockIdx.x * blockDim.x + threadIdx.x;
    if (i < n) {
        float v = in[i];
        bf16 h = __float2bfloat16_rn(v);
        hi[i] = h;
        lo[i] = __float2bfloat16_rn(v - __bfloat162float(h));
    }
}

// ---------------------------------------------------------------------------
// GEMM: C[M,768] = A[M,768] @ B[768,768]^T via bf16 3-product split.
// 128x128x32 tiles, 256 threads, cp.async double buffer.
// Output: fp32 (Cf) OR bf16 hi/lo pair (Chi/Clo), scaled by `scale`.
// ---------------------------------------------------------------------------
#define LDT 40            // smem halfs per tile row (32 + 8 pad)
#define TILE_B 10240      // 128*40*2
#define STAGE_B 40960     // 4 tiles
#define NKT (CC/32)       // 24

__global__ __launch_bounds__(256) void gemm_mma(
    const bf16* __restrict__ Ahi, const bf16* __restrict__ Alo,
    const bf16* __restrict__ Bhi, const bf16* __restrict__ Blo,
    float* __restrict__ Cf, bf16* __restrict__ Chi, bf16* __restrict__ Clo,
    float scale)
{
    extern __shared__ __align__(16) char smem[];
    const uint32_t sb = smem_u32(smem);
    const int tid = threadIdx.x, lane = tid & 31, wid = tid >> 5;
    const int wm = wid >> 2, wn = wid & 3;
    const int m0 = blockIdx.y * 128, n0 = blockIdx.x * 128;

    float c[4][4][4] = {};

    auto load_stage = [&](int kt, int s) {
        const int k0 = kt * 32;
        const uint32_t base = sb + s * STAGE_B;
#pragma unroll
        for (int i = 0; i < 2; i++) {
            int idx = tid + i * 256;
            int r = idx >> 2, c4 = idx & 3;
            size_t gA = (size_t)(m0 + r) * CC + k0 + c4 * 8;
            size_t gB = (size_t)(n0 + r) * CC + k0 + c4 * 8;
            uint32_t so = (uint32_t)(r * LDT + c4 * 8) * 2;
            cp16(base + so,              Ahi + gA);
            cp16(base + TILE_B + so,     Alo + gA);
            cp16(base + 2 * TILE_B + so, Bhi + gB);
            cp16(base + 3 * TILE_B + so, Blo + gB);
        }
        CP_COMMIT();
    };

    load_stage(0, 0);

    const int arow = wm * 64 + (lane & 7) + ((lane >> 3) & 1) * 8;
    const int brow = wn * 32 + (lane & 7) + (lane >> 4) * 8;

    for (int kt = 0; kt < NKT; kt++) {
        const int s = kt & 1;
        if (kt + 1 < NKT) { load_stage(kt + 1, s ^ 1); CP_WAIT1(); }
        else              { CP_WAIT0(); }
        __syncthreads();
        const uint32_t base = sb + s * STAGE_B;
#pragma unroll
        for (int k16 = 0; k16 < 2; k16++) {
            uint32_t aHi[4][4], aLo[4][4], bHi[2][4], bLo[2][4];
            const int acol = k16 * 16 + (lane >> 4) * 8;
            const int bcol = k16 * 16 + ((lane >> 3) & 1) * 8;
#pragma unroll
            for (int mi = 0; mi < 4; mi++) {
                uint32_t ad = base + (uint32_t)((arow + mi * 16) * LDT + acol) * 2;
                ldsm4(aHi[mi], ad);
                ldsm4(aLo[mi], ad + TILE_B);
            }
#pragma unroll
            for (int njp = 0; njp < 2; njp++) {
                uint32_t bd = base + 2 * TILE_B
                            + (uint32_t)((brow + njp * 16) * LDT + bcol) * 2;
                ldsm4(bHi[njp], bd);
                ldsm4(bLo[njp], bd + TILE_B);
            }
#pragma unroll
            for (int mi = 0; mi < 4; mi++)
#pragma unroll
                for (int nj = 0; nj < 4; nj++) {
                    const uint32_t* bh = &bHi[nj >> 1][(nj & 1) * 2];
                    const uint32_t* bl = &bLo[nj >> 1][(nj & 1) * 2];
                    mma16816(c[mi][nj], aHi[mi], bh);
                    mma16816(c[mi][nj], aHi[mi], bl);
                    mma16816(c[mi][nj], aLo[mi], bh);
                }
        }
        __syncthreads();
    }

    const int g = lane >> 2, q2 = (lane & 3) * 2;
#pragma unroll
    for (int mi = 0; mi < 4; mi++)
#pragma unroll
        for (int nj = 0; nj < 4; nj++) {
            int row = m0 + wm * 64 + mi * 16 + g;
            int col = n0 + wn * 32 + nj * 8 + q2;
            float v0 = c[mi][nj][0] * scale, v1 = c[mi][nj][1] * scale;
            float v2 = c[mi][nj][2] * scale, v3 = c[mi][nj][3] * scale;
            if (Cf) {
                *(float2*)&Cf[(size_t)row * CC + col]       = make_float2(v0, v1);
                *(float2*)&Cf[(size_t)(row + 8) * CC + col] = make_float2(v2, v3);
            } else {
                uint32_t ph, pl;
                split_pack(v0, v1, ph, pl);
                *(uint32_t*)&Chi[(size_t)row * CC + col] = ph;
                *(uint32_t*)&Clo[(size_t)row * CC + col] = pl;
                split_pack(v2, v3, ph, pl);
                *(uint32_t*)&Chi[(size_t)(row + 8) * CC + col] = ph;
                *(uint32_t*)&Clo[(size_t)(row + 8) * CC + col] = pl;
            }
        }
}

// ---------------------------------------------------------------------------
// Causal flash attention on mma.sync, bf16 3-product splits.
// Block: 64 q-rows x head, 128 threads (4 warps x 16 rows).
// P stays in registers (C-frag layout == A-frag layout for PV).
// ---------------------------------------------------------------------------
#define ATN_TILE_B 9216    // 64*72*2
#define ATN_STG_B  36864   // 4 tiles

__global__ __launch_bounds__(128) void attn_mma(
    const bf16* __restrict__ Qhi, const bf16* __restrict__ Qlo,
    const bf16* __restrict__ Khi, const bf16* __restrict__ Klo,
    const bf16* __restrict__ Vhi, const bf16* __restrict__ Vlo,
    bf16* __restrict__ Ohi, bf16* __restrict__ Olo)
{
    extern __shared__ __align__(16) char smem[];
    const uint32_t sb = smem_u32(smem);
    const int tid = threadIdx.x, lane = tid & 31, wid = tid >> 5;
    const int bh = blockIdx.y, b = bh / HH, h = bh - b * HH;
    const int qt = (int)gridDim.x - 1 - (int)blockIdx.x;  // heavy first
    const int q0 = qt * 64;
    const int wq0 = wid * 16;
    const uint32_t oQlo = ATN_TILE_B, oStg = 2 * ATN_TILE_B;

    // --- Q tiles (hi/lo) into smem, plain loads ---
    {
        const bf16* qh = Qhi + (size_t)(b * TT + q0) * CC + h * DD;
        const bf16* ql = Qlo + (size_t)(b * TT + q0) * CC + h * DD;
#pragma unroll
        for (int i = 0; i < 4; i++) {
            int idx = tid + i * 128;
            int r = idx >> 3, c8 = idx & 7;
            uint32_t so = (uint32_t)(r * 72 + c8 * 8) * 2;
            *(uint4*)(smem + so)        = *(const uint4*)(qh + (size_t)r * CC + c8 * 8);
            *(uint4*)(smem + oQlo + so) = *(const uint4*)(ql + (size_t)r * CC + c8 * 8);
        }
    }

    auto load_kv = [&](int kt, int s) {
        const uint32_t base = sb + oStg + s * ATN_STG_B;
        const size_t rb = (size_t)(b * TT + kt * 64) * CC + h * DD;
#pragma unroll
        for (int i = 0; i < 4; i++) {
            int idx = tid + i * 128;
            int r = idx >> 3, c8 = idx & 7;
            uint32_t so = (uint32_t)(r * 72 + c8 * 8) * 2;
            size_t go = rb + (size_t)r * CC + c8 * 8;
            cp16(base + so,                  Khi + go);
            cp16(base + ATN_TILE_B + so,     Klo + go);
            cp16(base + 2 * ATN_TILE_B + so, Vhi + go);
            cp16(base + 3 * ATN_TILE_B + so, Vlo + go);
        }
        CP_COMMIT();
    };

    load_kv(0, 0);
    __syncthreads();  // Q smem visible

    // --- Q fragments (fixed for the whole block) ---
    uint32_t qa_hi[4][4], qa_lo[4][4];
    {
        const int ar = wq0 + (lane & 7) + ((lane >> 3) & 1) * 8;
#pragma unroll
        for (int kk = 0; kk < 4; kk++) {
            const int ac = kk * 16 + (lane >> 4) * 8;
            uint32_t ad = sb + (uint32_t)(ar * 72 + ac) * 2;
            ldsm4(qa_hi[kk], ad);
            ldsm4(qa_lo[kk], ad + oQlo);
        }
    }

    float o[8][4] = {};
    float mr0 = -1e30f, mr1 = -1e30f, lr0 = 0.f, lr1 = 0.f;
    const int g = lane >> 2, q2 = (lane & 3) * 2;

    for (int kt = 0; kt <= qt; kt++) {
        const int s = kt & 1;
        if (kt < qt) { load_kv(kt + 1, s ^ 1); CP_WAIT1(); }
        else         { CP_WAIT0(); }
        __syncthreads();
        const uint32_t base = sb + oStg + s * ATN_STG_B;

        // --- S = Q K^T ---
        float cs[8][4] = {};
        {
            const int kr = (lane & 7) + (lane >> 4) * 8;
#pragma unroll
            for (int njp = 0; njp < 4; njp++)
#pragma unroll
                for (int kk = 0; kk < 4; kk++) {
                    const int kc = kk * 16 + ((lane >> 3) & 1) * 8;
                    uint32_t kd = base + (uint32_t)((kr + njp * 16) * 72 + kc) * 2;
                    uint32_t kb_hi[4], kb_lo[4];
                    ldsm4(kb_hi, kd);
                    ldsm4(kb_lo, kd + ATN_TILE_B);
#pragma unroll
                    for (int j = 0; j < 2; j++) {
                        mma16816(cs[njp * 2 + j], qa_hi[kk], &kb_hi[j * 2]);
                        mma16816(cs[njp * 2 + j], qa_hi[kk], &kb_lo[j * 2]);
                        mma16816(cs[njp * 2 + j], qa_lo[kk], &kb_hi[j * 2]);
                    }
                }
        }

        // --- causal mask (diag tile only) ---
        if (kt == qt) {
#pragma unroll
            for (int nj = 0; nj < 8; nj++)
#pragma unroll
                for (int e = 0; e < 4; e++) {
                    int qr = wq0 + g + ((e >> 1) << 3);
                    int kc = nj * 8 + q2 + (e & 1);
                    if (kc > qr) cs[nj][e] = -1e30f;
                }
        }

        // --- online softmax (rows g, g+8; quad lanes share a row) ---
        float mx0 = -1e30f, mx1 = -1e30f;
#pragma unroll
        for (int nj = 0; nj < 8; nj++) {
            mx0 = fmaxf(mx0, fmaxf(cs[nj][0], cs[nj][1]));
            mx1 = fmaxf(mx1, fmaxf(cs[nj][2], cs[nj][3]));
        }
        mx0 = fmaxf(mx0, __shfl_xor_sync(0xffffffffu, mx0, 1));
        mx0 = fmaxf(mx0, __shfl_xor_sync(0xffffffffu, mx0, 2));
        mx1 = fmaxf(mx1, __shfl_xor_sync(0xffffffffu, mx1, 1));
        mx1 = fmaxf(mx1, __shfl_xor_sync(0xffffffffu, mx1, 2));
        float mn0 = fmaxf(mr0, mx0), mn1 = fmaxf(mr1, mx1);
        float al0 = __expf(mr0 - mn0), al1 = __expf(mr1 - mn1);
        mr0 = mn0; mr1 = mn1;

        float s0 = 0.f, s1 = 0.f;
#pragma unroll
        for (int nj = 0; nj < 8; nj++) {
            cs[nj][0] = __expf(cs[nj][0] - mn0);
            cs[nj][1] = __expf(cs[nj][1] - mn0);
            cs[nj][2] = __expf(cs[nj][2] - mn1);
            cs[nj][3] = __expf(cs[nj][3] - mn1);
            s0 += cs[nj][0] + cs[nj][1];
            s1 += cs[nj][2] + cs[nj][3];
        }
        s0 += __shfl_xor_sync(0xffffffffu, s0, 1);
        s0 += __shfl_xor_sync(0xffffffffu, s0, 2);
        s1 += __shfl_xor_sync(0xffffffffu, s1, 1);
        s1 += __shfl_xor_sync(0xffffffffu, s1, 2);
        lr0 = lr0 * al0 + s0;
        lr1 = lr1 * al1 + s1;
#pragma unroll
        for (int dj = 0; dj < 8; dj++) {
            o[dj][0] *= al0; o[dj][1] *= al0;
            o[dj][2] *= al1; o[dj][3] *= al1;
        }

        // --- split P into bf16 hi/lo A-fragments (register-only) ---
        uint32_t pa_hi[4][4], pa_lo[4][4];
#pragma unroll
        for (int kk2 = 0; kk2 < 4; kk2++) {
            split_pack(cs[2 * kk2][0],     cs[2 * kk2][1],     pa_hi[kk2][0], pa_lo[kk2][0]);
            split_pack(cs[2 * kk2][2],     cs[2 * kk2][3],     pa_hi[kk2][1], pa_lo[kk2][1]);
            split_pack(cs[2 * kk2 + 1][0], cs[2 * kk2 + 1][1], pa_hi[kk2][2], pa_lo[kk2][2]);
            split_pack(cs[2 * kk2 + 1][2], cs[2 * kk2 + 1][3], pa_hi[kk2][3], pa_lo[kk2][3]);
        }

        // --- O += P V (V via ldmatrix.trans from [kv][d]) ---
        {
            const int vr = (lane & 7) + ((lane >> 3) & 1) * 8;
#pragma unroll
            for (int djp = 0; djp < 4; djp++)
#pragma unroll
                for (int kk2 = 0; kk2 < 4; kk2++) {
                    const int vc = djp * 16 + (lane >> 4) * 8;
                    uint32_t vd = base + 2 * ATN_TILE_B
                                + (uint32_t)((vr + kk2 * 16) * 72 + vc) * 2;
                    uint32_t vb_hi[4], vb_lo[4];
                    ldsm4t(vb_hi, vd);
                    ldsm4t(vb_lo, vd + ATN_TILE_B);
#pragma unroll
                    for (int j = 0; j < 2; j++) {
                        mma16816(o[djp * 2 + j], pa_hi[kk2], &vb_hi[j * 2]);
                        mma16816(o[djp * 2 + j], pa_hi[kk2], &vb_lo[j * 2]);
                        mma16816(o[djp * 2 + j], pa_lo[kk2], &vb_hi[j * 2]);
                    }
                }
        }
        __syncthreads();
    }

    // --- epilogue: normalize, split to bf16 hi/lo, store ---
    float inv0 = 1.f / lr0, inv1 = 1.f / lr1;
    const size_t r0 = (size_t)(b * TT + q0 + wq0 + g) * CC + h * DD;
    const size_t r1 = r0 + (size_t)8 * CC;
#pragma unroll
    for (int dj = 0; dj < 8; dj++) {
        int col = dj * 8 + q2;
        uint32_t ph, pl;
        split_pack(o[dj][0] * inv0, o[dj][1] * inv0, ph, pl);
        *(uint32_t*)&Ohi[r0 + col] = ph;
        *(uint32_t*)&Olo[r0 + col] = pl;
        split_pack(o[dj][2] * inv1, o[dj][3] * inv1, ph, pl);
        *(uint32_t*)&Ohi[r1 + col] = ph;
        *(uint32_t*)&Olo[r1 + col] = pl;
    }
}

// ---------------------------------------------------------------------------
extern "C" void kernel_launch(void* const* d_in, const int* in_sizes, int n_in,
                              void* d_out, int out_size) {
    const float* x  = (const float*)d_in[0];
    const float* Wq = (const float*)d_in[1];
    const float* Wk = (const float*)d_in[2];
    const float* Wv = (const float*)d_in[3];
    const float* Wp = (const float*)d_in[4];
    float* out = (float*)d_out;

    bf16 *xhi, *xlo, *whi, *wlo, *qhi, *qlo, *khi, *klo, *vhi, *vlo, *ohi, *olo;
    cudaGetSymbolAddress((void**)&xhi, g_xhi);
    cudaGetSymbolAddress((void**)&xlo, g_xlo);
    cudaGetSymbolAddress((void**)&whi, g_whi);
    cudaGetSymbolAddress((void**)&wlo, g_wlo);
    cudaGetSymbolAddress((void**)&qhi, g_qhi);
    cudaGetSymbolAddress((void**)&qlo, g_qlo);
    cudaGetSymbolAddress((void**)&khi, g_khi);
    cudaGetSymbolAddress((void**)&klo, g_klo);
    cudaGetSymbolAddress((void**)&vhi, g_vhi);
    cudaGetSymbolAddress((void**)&vlo, g_vlo);
    cudaGetSymbolAddress((void**)&ohi, g_ohi);
    cudaGetSymbolAddress((void**)&olo, g_olo);

    cudaFuncSetAttribute(gemm_mma,
                         cudaFuncAttributeMaxDynamicSharedMemorySize, 2 * STAGE_B);
    const int smem_attn = 2 * ATN_TILE_B + 2 * ATN_STG_B;  // 92160
    cudaFuncSetAttribute(attn_mma,
                         cudaFuncAttributeMaxDynamicSharedMemorySize, smem_attn);

    const int NX = MM * CC, NW = CC * CC;
    split_fp32<<<(NX + 255) / 256, 256>>>(x, xhi, xlo, NX);
    split_fp32<<<(NW + 255) / 256, 256>>>(Wq, whi + 0 * NW, wlo + 0 * NW, NW);
    split_fp32<<<(NW + 255) / 256, 256>>>(Wk, whi + 1 * NW, wlo + 1 * NW, NW);
    split_fp32<<<(NW + 255) / 256, 256>>>(Wv, whi + 2 * NW, wlo + 2 * NW, NW);
    split_fp32<<<(NW + 255) / 256, 256>>>(Wp, whi + 3 * NW, wlo + 3 * NW, NW);

    dim3 gg(CC / 128, MM / 128);  // (6, 64)
    // Q projection pre-scaled by D^-0.5 = 0.125
    gemm_mma<<<gg, 256, 2 * STAGE_B>>>(xhi, xlo, whi + 0 * NW, wlo + 0 * NW,
                                       nullptr, qhi, qlo, 0.125f);
    gemm_mma<<<gg, 256, 2 * STAGE_B>>>(xhi, xlo, whi + 1 * NW, wlo + 1 * NW,
                                       nullptr, khi, klo, 1.0f);
    gemm_mma<<<gg, 256, 2 * STAGE_B>>>(xhi, xlo, whi + 2 * NW, wlo + 2 * NW,
                                       nullptr, vhi, vlo, 1.0f);

    attn_mma<<<dim3(TT / 64, BB * HH), 128, smem_attn>>>(qhi, qlo, khi, klo,
                                                         vhi, vlo, ohi, olo);

    gemm_mma<<<gg, 256, 2 * STAGE_B>>>(ohi, olo, whi + 3 * NW, wlo + 3 * NW,
                                       out, nullptr, nullptr, 1.0f);
}

// round 4
// speedup vs baseline: 3.3859x; 1.1167x over previous
#include <cuda_runtime.h>
#include <cuda_bf16.h>
#include <cstdint>

#define BB 4
#define TT 2048
#define HH 12
#define DD 64
#define CC 768
#define MM (BB*TT)

typedef __nv_bfloat16 bf16;

// ---------------------------------------------------------------------------
// Scratch (__device__ globals; alloc-free rule)
// ---------------------------------------------------------------------------
__device__ bf16 g_xhi[MM*CC], g_xlo[MM*CC];
__device__ bf16 g_whi[4*CC*CC], g_wlo[4*CC*CC];   // Wq | Wk | Wv | Wp
__device__ bf16 g_qhi[MM*CC], g_qlo[MM*CC];
__device__ bf16 g_khi[MM*CC], g_klo[MM*CC];
__device__ bf16 g_vhi[MM*CC], g_vlo[MM*CC];
__device__ bf16 g_ohi[MM*CC], g_olo[MM*CC];

// ---------------------------------------------------------------------------
// helpers
// ---------------------------------------------------------------------------
__device__ __forceinline__ uint32_t smem_u32(const void* p) {
    uint32_t a;
    asm("{ .reg .u64 t; cvta.to.shared.u64 t, %1; cvt.u32.u64 %0, t; }"
        : "=r"(a) : "l"(p));
    return a;
}
__device__ __forceinline__ void ldsm4(uint32_t* r, uint32_t addr) {
    asm volatile("ldmatrix.sync.aligned.m8n8.x4.shared.b16 {%0,%1,%2,%3}, [%4];\n"
                 : "=r"(r[0]), "=r"(r[1]), "=r"(r[2]), "=r"(r[3]) : "r"(addr));
}
__device__ __forceinline__ void ldsm4t(uint32_t* r, uint32_t addr) {
    asm volatile("ldmatrix.sync.aligned.m8n8.x4.trans.shared.b16 {%0,%1,%2,%3}, [%4];\n"
                 : "=r"(r[0]), "=r"(r[1]), "=r"(r[2]), "=r"(r[3]) : "r"(addr));
}
__device__ __forceinline__ void mma16816(float* c, const uint32_t* a, const uint32_t* b) {
    asm volatile(
        "mma.sync.aligned.m16n8k16.row.col.f32.bf16.bf16.f32 "
        "{%0,%1,%2,%3}, {%4,%5,%6,%7}, {%8,%9}, {%0,%1,%2,%3};\n"
        : "+f"(c[0]), "+f"(c[1]), "+f"(c[2]), "+f"(c[3])
        : "r"(a[0]), "r"(a[1]), "r"(a[2]), "r"(a[3]), "r"(b[0]), "r"(b[1]));
}
__device__ __forceinline__ void cp16(uint32_t dst, const void* src) {
    asm volatile("cp.async.cg.shared.global [%0], [%1], 16;\n" :: "r"(dst), "l"(src));
}
#define CP_COMMIT() asm volatile("cp.async.commit_group;\n")
#define CP_WAIT0()  asm volatile("cp.async.wait_group 0;\n")
#define CP_WAIT1()  asm volatile("cp.async.wait_group 1;\n")

__device__ __forceinline__ float ex2(float x) {
    float y; asm("ex2.approx.f32 %0, %1;" : "=f"(y) : "f"(x)); return y;
}

// pack (x0 -> low half, x1 -> high half) as bf16x2 hi + residual lo
__device__ __forceinline__ void split_pack(float x0, float x1,
                                           uint32_t& phi, uint32_t& plo) {
    uint32_t h;
    asm("cvt.rn.bf16x2.f32 %0, %1, %2;" : "=r"(h) : "f"(x1), "f"(x0));
    float h0 = __uint_as_float(h << 16);
    float h1 = __uint_as_float(h & 0xffff0000u);
    asm("cvt.rn.bf16x2.f32 %0, %1, %2;" : "=r"(plo) : "f"(x1 - h1), "f"(x0 - h0));
    phi = h;
}

// ---------------------------------------------------------------------------
// fp32 -> (bf16 hi, bf16 lo) split
// ---------------------------------------------------------------------------
__global__ void split_fp32(const float* __restrict__ in,
                           bf16* __restrict__ hi, bf16* __restrict__ lo, int n) {
    int i = blockIdx.x * blockDim.x + threadIdx.x;
    if (i < n) {
        float v = in[i];
        bf16 h = __float2bfloat16_rn(v);
        hi[i] = h;
        lo[i] = __float2bfloat16_rn(v - __bfloat162float(h));
    }
}

// ---------------------------------------------------------------------------
// Shared GEMM core: 128x128x32 tiles, 256 threads, cp.async double buffer,
// bf16 3-product split. Accumulates c[4][4][4] for warp tile 64x32.
// ---------------------------------------------------------------------------
#define LDT 40            // smem halfs per tile row (32 + 8 pad)
#define TILE_B 10240      // 128*40*2
#define STAGE_B 40960     // 4 tiles
#define NKT (CC/32)       // 24

struct GemmCore {
    uint32_t sb;
    int tid, lane, wid, wm, wn, m0, n0;
    const bf16 *Ahi, *Alo, *Bhi, *Blo;
    float c[4][4][4];

    __device__ __forceinline__ void load_stage(int kt, int s) {
        const int k0 = kt * 32;
        const uint32_t base = sb + s * STAGE_B;
#pragma unroll
        for (int i = 0; i < 2; i++) {
            int idx = tid + i * 256;
            int r = idx >> 2, c4 = idx & 3;
            size_t gA = (size_t)(m0 + r) * CC + k0 + c4 * 8;
            size_t gB = (size_t)(n0 + r) * CC + k0 + c4 * 8;
            uint32_t so = (uint32_t)(r * LDT + c4 * 8) * 2;
            cp16(base + so,              Ahi + gA);
            cp16(base + TILE_B + so,     Alo + gA);
            cp16(base + 2 * TILE_B + so, Bhi + gB);
            cp16(base + 3 * TILE_B + so, Blo + gB);
        }
        CP_COMMIT();
    }

    __device__ __forceinline__ void run() {
#pragma unroll
        for (int a = 0; a < 4; a++)
#pragma unroll
            for (int bq = 0; bq < 4; bq++)
#pragma unroll
                for (int e = 0; e < 4; e++) c[a][bq][e] = 0.f;

        load_stage(0, 0);
        const int arow = wm * 64 + (lane & 7) + ((lane >> 3) & 1) * 8;
        const int brow = wn * 32 + (lane & 7) + (lane >> 4) * 8;

        for (int kt = 0; kt < NKT; kt++) {
            const int s = kt & 1;
            if (kt + 1 < NKT) { load_stage(kt + 1, s ^ 1); CP_WAIT1(); }
            else              { CP_WAIT0(); }
            __syncthreads();
            const uint32_t base = sb + s * STAGE_B;
#pragma unroll
            for (int k16 = 0; k16 < 2; k16++) {
                uint32_t aHi[4][4], aLo[4][4], bHi[2][4], bLo[2][4];
                const int acol = k16 * 16 + (lane >> 4) * 8;
                const int bcol = k16 * 16 + ((lane >> 3) & 1) * 8;
#pragma unroll
                for (int mi = 0; mi < 4; mi++) {
                    uint32_t ad = base + (uint32_t)((arow + mi * 16) * LDT + acol) * 2;
                    ldsm4(aHi[mi], ad);
                    ldsm4(aLo[mi], ad + TILE_B);
                }
#pragma unroll
                for (int njp = 0; njp < 2; njp++) {
                    uint32_t bd = base + 2 * TILE_B
                                + (uint32_t)((brow + njp * 16) * LDT + bcol) * 2;
                    ldsm4(bHi[njp], bd);
                    ldsm4(bLo[njp], bd + TILE_B);
                }
#pragma unroll
                for (int mi = 0; mi < 4; mi++)
#pragma unroll
                    for (int nj = 0; nj < 4; nj++) {
                        const uint32_t* bh = &bHi[nj >> 1][(nj & 1) * 2];
                        const uint32_t* bl = &bLo[nj >> 1][(nj & 1) * 2];
                        mma16816(c[mi][nj], aHi[mi], bh);
                        mma16816(c[mi][nj], aHi[mi], bl);
                        mma16816(c[mi][nj], aLo[mi], bh);
                    }
            }
            __syncthreads();
        }
    }
};

// ---------------------------------------------------------------------------
// Fused QKV projection: C[M,2304] = X @ [Wq;Wk;Wv]^T, split-bf16 outputs.
// Q segment pre-scaled by D^-0.5 * log2(e).
// ---------------------------------------------------------------------------
__global__ __launch_bounds__(256) void gemm_qkv(
    const bf16* __restrict__ Xhi, const bf16* __restrict__ Xlo,
    const bf16* __restrict__ Whi, const bf16* __restrict__ Wlo,
    bf16* __restrict__ qhi, bf16* __restrict__ qlo,
    bf16* __restrict__ khi, bf16* __restrict__ klo,
    bf16* __restrict__ vhi, bf16* __restrict__ vlo)
{
    extern __shared__ __align__(16) char smem[];
    GemmCore g;
    g.sb = smem_u32(smem);
    g.tid = threadIdx.x; g.lane = g.tid & 31; g.wid = g.tid >> 5;
    g.wm = g.wid >> 2; g.wn = g.wid & 3;
    g.m0 = blockIdx.y * 128; g.n0 = blockIdx.x * 128;
    g.Ahi = Xhi; g.Alo = Xlo; g.Bhi = Whi; g.Blo = Wlo;
    g.run();

    const int seg = g.n0 / CC;            // 0=q, 1=k, 2=v (segments 128-aligned)
    const int nloc = g.n0 - seg * CC;
    bf16 *Dhi, *Dlo;
    float scale;
    if (seg == 0)      { Dhi = qhi; Dlo = qlo; scale = 0.125f * 1.4426950408889634f; }
    else if (seg == 1) { Dhi = khi; Dlo = klo; scale = 1.0f; }
    else               { Dhi = vhi; Dlo = vlo; scale = 1.0f; }

    const int gr = g.lane >> 2, q2 = (g.lane & 3) * 2;
#pragma unroll
    for (int mi = 0; mi < 4; mi++)
#pragma unroll
        for (int nj = 0; nj < 4; nj++) {
            int row = g.m0 + g.wm * 64 + mi * 16 + gr;
            int col = nloc + g.wn * 32 + nj * 8 + q2;
            uint32_t ph, pl;
            split_pack(g.c[mi][nj][0] * scale, g.c[mi][nj][1] * scale, ph, pl);
            *(uint32_t*)&Dhi[(size_t)row * CC + col] = ph;
            *(uint32_t*)&Dlo[(size_t)row * CC + col] = pl;
            split_pack(g.c[mi][nj][2] * scale, g.c[mi][nj][3] * scale, ph, pl);
            *(uint32_t*)&Dhi[(size_t)(row + 8) * CC + col] = ph;
            *(uint32_t*)&Dlo[(size_t)(row + 8) * CC + col] = pl;
        }
}

// ---------------------------------------------------------------------------
// Output projection: out[M,768] = O @ Wp^T, fp32 output.
// ---------------------------------------------------------------------------
__global__ __launch_bounds__(256) void gemm_proj(
    const bf16* __restrict__ Ahi, const bf16* __restrict__ Alo,
    const bf16* __restrict__ Bhi, const bf16* __restrict__ Blo,
    float* __restrict__ Cf)
{
    extern __shared__ __align__(16) char smem[];
    GemmCore g;
    g.sb = smem_u32(smem);
    g.tid = threadIdx.x; g.lane = g.tid & 31; g.wid = g.tid >> 5;
    g.wm = g.wid >> 2; g.wn = g.wid & 3;
    g.m0 = blockIdx.y * 128; g.n0 = blockIdx.x * 128;
    g.Ahi = Ahi; g.Alo = Alo; g.Bhi = Bhi; g.Blo = Blo;
    g.run();

    const int gr = g.lane >> 2, q2 = (g.lane & 3) * 2;
#pragma unroll
    for (int mi = 0; mi < 4; mi++)
#pragma unroll
        for (int nj = 0; nj < 4; nj++) {
            int row = g.m0 + g.wm * 64 + mi * 16 + gr;
            int col = g.n0 + g.wn * 32 + nj * 8 + q2;
            *(float2*)&Cf[(size_t)row * CC + col] =
                make_float2(g.c[mi][nj][0], g.c[mi][nj][1]);
            *(float2*)&Cf[(size_t)(row + 8) * CC + col] =
                make_float2(g.c[mi][nj][2], g.c[mi][nj][3]);
        }
}

// ---------------------------------------------------------------------------
// Causal flash attention on mma.sync, bf16 3-product splits, exp2 softmax.
// Block: 64 q-rows x head, 128 threads (4 warps x 16 rows).
// ---------------------------------------------------------------------------
#define ATN_TILE_B 9216    // 64*72*2
#define ATN_STG_B  36864   // 4 tiles

__global__ __launch_bounds__(128) void attn_mma(
    const bf16* __restrict__ Qhi, const bf16* __restrict__ Qlo,
    const bf16* __restrict__ Khi, const bf16* __restrict__ Klo,
    const bf16* __restrict__ Vhi, const bf16* __restrict__ Vlo,
    bf16* __restrict__ Ohi, bf16* __restrict__ Olo)
{
    extern __shared__ __align__(16) char smem[];
    const uint32_t sb = smem_u32(smem);
    const int tid = threadIdx.x, lane = tid & 31, wid = tid >> 5;
    const int bh = blockIdx.y, b = bh / HH, h = bh - b * HH;
    const int qt = (int)gridDim.x - 1 - (int)blockIdx.x;  // heavy first
    const int q0 = qt * 64;
    const int wq0 = wid * 16;
    const uint32_t oQlo = ATN_TILE_B, oStg = 2 * ATN_TILE_B;

    // --- Q tiles (hi/lo) into smem ---
    {
        const bf16* qh = Qhi + (size_t)(b * TT + q0) * CC + h * DD;
        const bf16* ql = Qlo + (size_t)(b * TT + q0) * CC + h * DD;
#pragma unroll
        for (int i = 0; i < 4; i++) {
            int idx = tid + i * 128;
            int r = idx >> 3, c8 = idx & 7;
            uint32_t so = (uint32_t)(r * 72 + c8 * 8) * 2;
            *(uint4*)(smem + so)        = *(const uint4*)(qh + (size_t)r * CC + c8 * 8);
            *(uint4*)(smem + oQlo + so) = *(const uint4*)(ql + (size_t)r * CC + c8 * 8);
        }
    }

    auto load_kv = [&](int kt, int s) {
        const uint32_t base = sb + oStg + s * ATN_STG_B;
        const size_t rb = (size_t)(b * TT + kt * 64) * CC + h * DD;
#pragma unroll
        for (int i = 0; i < 4; i++) {
            int idx = tid + i * 128;
            int r = idx >> 3, c8 = idx & 7;
            uint32_t so = (uint32_t)(r * 72 + c8 * 8) * 2;
            size_t go = rb + (size_t)r * CC + c8 * 8;
            cp16(base + so,                  Khi + go);
            cp16(base + ATN_TILE_B + so,     Klo + go);
            cp16(base + 2 * ATN_TILE_B + so, Vhi + go);
            cp16(base + 3 * ATN_TILE_B + so, Vlo + go);
        }
        CP_COMMIT();
    };

    load_kv(0, 0);
    __syncthreads();

    // --- Q fragments (fixed for the whole block) ---
    uint32_t qa_hi[4][4], qa_lo[4][4];
    {
        const int ar = wq0 + (lane & 7) + ((lane >> 3) & 1) * 8;
#pragma unroll
        for (int kk = 0; kk < 4; kk++) {
            const int ac = kk * 16 + (lane >> 4) * 8;
            uint32_t ad = sb + (uint32_t)(ar * 72 + ac) * 2;
            ldsm4(qa_hi[kk], ad);
            ldsm4(qa_lo[kk], ad + oQlo);
        }
    }

    float o[8][4] = {};
    float mr0 = -1e30f, mr1 = -1e30f, lr0 = 0.f, lr1 = 0.f;
    const int g = lane >> 2, q2 = (lane & 3) * 2;

    for (int kt = 0; kt <= qt; kt++) {
        const int s = kt & 1;
        if (kt < qt) { load_kv(kt + 1, s ^ 1); CP_WAIT1(); }
        else         { CP_WAIT0(); }
        __syncthreads();
        const uint32_t base = sb + oStg + s * ATN_STG_B;

        // --- S = Q K^T (pre-scaled by 0.125*log2e via Q) ---
        float cs[8][4] = {};
        {
            const int kr = (lane & 7) + (lane >> 4) * 8;
#pragma unroll
            for (int njp = 0; njp < 4; njp++)
#pragma unroll
                for (int kk = 0; kk < 4; kk++) {
                    const int kc = kk * 16 + ((lane >> 3) & 1) * 8;
                    uint32_t kd = base + (uint32_t)((kr + njp * 16) * 72 + kc) * 2;
                    uint32_t kb_hi[4], kb_lo[4];
                    ldsm4(kb_hi, kd);
                    ldsm4(kb_lo, kd + ATN_TILE_B);
#pragma unroll
                    for (int j = 0; j < 2; j++) {
                        mma16816(cs[njp * 2 + j], qa_hi[kk], &kb_hi[j * 2]);
                        mma16816(cs[njp * 2 + j], qa_hi[kk], &kb_lo[j * 2]);
                        mma16816(cs[njp * 2 + j], qa_lo[kk], &kb_hi[j * 2]);
                    }
                }
        }

        // --- causal mask (diag tile only) ---
        if (kt == qt) {
#pragma unroll
            for (int nj = 0; nj < 8; nj++)
#pragma unroll
                for (int e = 0; e < 4; e++) {
                    int qr = wq0 + g + ((e >> 1) << 3);
                    int kc = nj * 8 + q2 + (e & 1);
                    if (kc > qr) cs[nj][e] = -1e30f;
                }
        }

        // --- online softmax (base-2) ---
        float mx0 = -1e30f, mx1 = -1e30f;
#pragma unroll
        for (int nj = 0; nj < 8; nj++) {
            mx0 = fmaxf(mx0, fmaxf(cs[nj][0], cs[nj][1]));
            mx1 = fmaxf(mx1, fmaxf(cs[nj][2], cs[nj][3]));
        }
        mx0 = fmaxf(mx0, __shfl_xor_sync(0xffffffffu, mx0, 1));
        mx0 = fmaxf(mx0, __shfl_xor_sync(0xffffffffu, mx0, 2));
        mx1 = fmaxf(mx1, __shfl_xor_sync(0xffffffffu, mx1, 1));
        mx1 = fmaxf(mx1, __shfl_xor_sync(0xffffffffu, mx1, 2));
        float mn0 = fmaxf(mr0, mx0), mn1 = fmaxf(mr1, mx1);
        float al0 = ex2(mr0 - mn0), al1 = ex2(mr1 - mn1);
        mr0 = mn0; mr1 = mn1;

        float s0 = 0.f, s1 = 0.f;
#pragma unroll
        for (int nj = 0; nj < 8; nj++) {
            cs[nj][0] = ex2(cs[nj][0] - mn0);
            cs[nj][1] = ex2(cs[nj][1] - mn0);
            cs[nj][2] = ex2(cs[nj][2] - mn1);
            cs[nj][3] = ex2(cs[nj][3] - mn1);
            s0 += cs[nj][0] + cs[nj][1];
            s1 += cs[nj][2] + cs[nj][3];
        }
        s0 += __shfl_xor_sync(0xffffffffu, s0, 1);
        s0 += __shfl_xor_sync(0xffffffffu, s0, 2);
        s1 += __shfl_xor_sync(0xffffffffu, s1, 1);
        s1 += __shfl_xor_sync(0xffffffffu, s1, 2);
        lr0 = lr0 * al0 + s0;
        lr1 = lr1 * al1 + s1;
#pragma unroll
        for (int dj = 0; dj < 8; dj++) {
            o[dj][0] *= al0; o[dj][1] *= al0;
            o[dj][2] *= al1; o[dj][3] *= al1;
        }

        // --- split P into bf16 hi/lo A-fragments (register-only) ---
        uint32_t pa_hi[4][4], pa_lo[4][4];
#pragma unroll
        for (int kk2 = 0; kk2 < 4; kk2++) {
            split_pack(cs[2 * kk2][0],     cs[2 * kk2][1],     pa_hi[kk2][0], pa_lo[kk2][0]);
            split_pack(cs[2 * kk2][2],     cs[2 * kk2][3],     pa_hi[kk2][1], pa_lo[kk2][1]);
            split_pack(cs[2 * kk2 + 1][0], cs[2 * kk2 + 1][1], pa_hi[kk2][2], pa_lo[kk2][2]);
            split_pack(cs[2 * kk2 + 1][2], cs[2 * kk2 + 1][3], pa_hi[kk2][3], pa_lo[kk2][3]);
        }

        // --- O += P V (V via ldmatrix.trans) ---
        {
            const int vr = (lane & 7) + ((lane >> 3) & 1) * 8;
#pragma unroll
            for (int djp = 0; djp < 4; djp++)
#pragma unroll
                for (int kk2 = 0; kk2 < 4; kk2++) {
                    const int vc = djp * 16 + (lane >> 4) * 8;
                    uint32_t vd = base + 2 * ATN_TILE_B
                                + (uint32_t)((vr + kk2 * 16) * 72 + vc) * 2;
                    uint32_t vb_hi[4], vb_lo[4];
                    ldsm4t(vb_hi, vd);
                    ldsm4t(vb_lo, vd + ATN_TILE_B);
#pragma unroll
                    for (int j = 0; j < 2; j++) {
                        mma16816(o[djp * 2 + j], pa_hi[kk2], &vb_hi[j * 2]);
                        mma16816(o[djp * 2 + j], pa_hi[kk2], &vb_lo[j * 2]);
                        mma16816(o[djp * 2 + j], pa_lo[kk2], &vb_hi[j * 2]);
                    }
                }
        }
        __syncthreads();
    }

    // --- epilogue: normalize, split to bf16 hi/lo, store ---
    float inv0 = 1.f / lr0, inv1 = 1.f / lr1;
    const size_t r0 = (size_t)(b * TT + q0 + wq0 + g) * CC + h * DD;
    const size_t r1 = r0 + (size_t)8 * CC;
#pragma unroll
    for (int dj = 0; dj < 8; dj++) {
        int col = dj * 8 + q2;
        uint32_t ph, pl;
        split_pack(o[dj][0] * inv0, o[dj][1] * inv0, ph, pl);
        *(uint32_t*)&Ohi[r0 + col] = ph;
        *(uint32_t*)&Olo[r0 + col] = pl;
        split_pack(o[dj][2] * inv1, o[dj][3] * inv1, ph, pl);
        *(uint32_t*)&Ohi[r1 + col] = ph;
        *(uint32_t*)&Olo[r1 + col] = pl;
    }
}

// ---------------------------------------------------------------------------
extern "C" void kernel_launch(void* const* d_in, const int* in_sizes, int n_in,
                              void* d_out, int out_size) {
    const float* x  = (const float*)d_in[0];
    const float* Wq = (const float*)d_in[1];
    const float* Wk = (const float*)d_in[2];
    const float* Wv = (const float*)d_in[3];
    const float* Wp = (const float*)d_in[4];
    float* out = (float*)d_out;

    bf16 *xhi, *xlo, *whi, *wlo, *qhi, *qlo, *khi, *klo, *vhi, *vlo, *ohi, *olo;
    cudaGetSymbolAddress((void**)&xhi, g_xhi);
    cudaGetSymbolAddress((void**)&xlo, g_xlo);
    cudaGetSymbolAddress((void**)&whi, g_whi);
    cudaGetSymbolAddress((void**)&wlo, g_wlo);
    cudaGetSymbolAddress((void**)&qhi, g_qhi);
    cudaGetSymbolAddress((void**)&qlo, g_qlo);
    cudaGetSymbolAddress((void**)&khi, g_khi);
    cudaGetSymbolAddress((void**)&klo, g_klo);
    cudaGetSymbolAddress((void**)&vhi, g_vhi);
    cudaGetSymbolAddress((void**)&vlo, g_vlo);
    cudaGetSymbolAddress((void**)&ohi, g_ohi);
    cudaGetSymbolAddress((void**)&olo, g_olo);

    cudaFuncSetAttribute(gemm_qkv,
                         cudaFuncAttributeMaxDynamicSharedMemorySize, 2 * STAGE_B);
    cudaFuncSetAttribute(gemm_proj,
                         cudaFuncAttributeMaxDynamicSharedMemorySize, 2 * STAGE_B);
    const int smem_attn = 2 * ATN_TILE_B + 2 * ATN_STG_B;  // 92160
    cudaFuncSetAttribute(attn_mma,
                         cudaFuncAttributeMaxDynamicSharedMemorySize, smem_attn);

    const int NX = MM * CC, NW = CC * CC;
    split_fp32<<<(NX + 255) / 256, 256>>>(x, xhi, xlo, NX);
    split_fp32<<<(NW + 255) / 256, 256>>>(Wq, whi + 0 * NW, wlo + 0 * NW, NW);
    split_fp32<<<(NW + 255) / 256, 256>>>(Wk, whi + 1 * NW, wlo + 1 * NW, NW);
    split_fp32<<<(NW + 255) / 256, 256>>>(Wv, whi + 2 * NW, wlo + 2 * NW, NW);
    split_fp32<<<(NW + 255) / 256, 256>>>(Wp, whi + 3 * NW, wlo + 3 * NW, NW);

    // fused QKV projection: N = 2304
    gemm_qkv<<<dim3(3 * CC / 128, MM / 128), 256, 2 * STAGE_B>>>(
        xhi, xlo, whi, wlo, qhi, qlo, khi, klo, vhi, vlo);

    attn_mma<<<dim3(TT / 64, BB * HH), 128, smem_attn>>>(qhi, qlo, khi, klo,
                                                         vhi, vlo, ohi, olo);

    gemm_proj<<<dim3(CC / 128, MM / 128), 256, 2 * STAGE_B>>>(
        ohi, olo, whi + 3 * NW, wlo + 3 * NW, out);
}

// round 5
// speedup vs baseline: 3.4215x; 1.0105x over previous
#include <cuda_runtime.h>
#include <cuda_bf16.h>
#include <cstdint>

#define BB 4
#define TT 2048
#define HH 12
#define DD 64
#define CC 768
#define MM (BB*TT)

typedef __nv_bfloat16 bf16;

// ---------------------------------------------------------------------------
// Scratch (__device__ globals; alloc-free rule)
// ---------------------------------------------------------------------------
__device__ bf16 g_xhi[MM*CC], g_xlo[MM*CC];
__device__ bf16 g_whi[4*CC*CC], g_wlo[4*CC*CC];   // Wq | Wk | Wv | Wp
__device__ bf16 g_qhi[MM*CC], g_qlo[MM*CC];
__device__ bf16 g_khi[MM*CC], g_klo[MM*CC];
__device__ bf16 g_vhi[MM*CC], g_vlo[MM*CC];
__device__ bf16 g_ohi[MM*CC], g_olo[MM*CC];

// ---------------------------------------------------------------------------
// helpers
// ---------------------------------------------------------------------------
__device__ __forceinline__ uint32_t smem_u32(const void* p) {
    uint32_t a;
    asm("{ .reg .u64 t; cvta.to.shared.u64 t, %1; cvt.u32.u64 %0, t; }"
        : "=r"(a) : "l"(p));
    return a;
}
__device__ __forceinline__ void ldsm4(uint32_t* r, uint32_t addr) {
    asm volatile("ldmatrix.sync.aligned.m8n8.x4.shared.b16 {%0,%1,%2,%3}, [%4];\n"
                 : "=r"(r[0]), "=r"(r[1]), "=r"(r[2]), "=r"(r[3]) : "r"(addr));
}
__device__ __forceinline__ void ldsm4t(uint32_t* r, uint32_t addr) {
    asm volatile("ldmatrix.sync.aligned.m8n8.x4.trans.shared.b16 {%0,%1,%2,%3}, [%4];\n"
                 : "=r"(r[0]), "=r"(r[1]), "=r"(r[2]), "=r"(r[3]) : "r"(addr));
}
__device__ __forceinline__ void mma16816(float* c, const uint32_t* a, const uint32_t* b) {
    asm volatile(
        "mma.sync.aligned.m16n8k16.row.col.f32.bf16.bf16.f32 "
        "{%0,%1,%2,%3}, {%4,%5,%6,%7}, {%8,%9}, {%0,%1,%2,%3};\n"
        : "+f"(c[0]), "+f"(c[1]), "+f"(c[2]), "+f"(c[3])
        : "r"(a[0]), "r"(a[1]), "r"(a[2]), "r"(a[3]), "r"(b[0]), "r"(b[1]));
}
__device__ __forceinline__ void cp16(uint32_t dst, const void* src) {
    asm volatile("cp.async.cg.shared.global [%0], [%1], 16;\n" :: "r"(dst), "l"(src));
}
#define CP_COMMIT() asm volatile("cp.async.commit_group;\n")
#define CP_WAIT0()  asm volatile("cp.async.wait_group 0;\n")
#define CP_WAIT1()  asm volatile("cp.async.wait_group 1;\n")

__device__ __forceinline__ float ex2(float x) {
    float y; asm("ex2.approx.f32 %0, %1;" : "=f"(y) : "f"(x)); return y;
}

// pack (x0 -> low half, x1 -> high half) as bf16x2 hi + residual lo
__device__ __forceinline__ void split_pack(float x0, float x1,
                                           uint32_t& phi, uint32_t& plo) {
    uint32_t h;
    asm("cvt.rn.bf16x2.f32 %0, %1, %2;" : "=r"(h) : "f"(x1), "f"(x0));
    float h0 = __uint_as_float(h << 16);
    float h1 = __uint_as_float(h & 0xffff0000u);
    asm("cvt.rn.bf16x2.f32 %0, %1, %2;" : "=r"(plo) : "f"(x1 - h1), "f"(x0 - h0));
    phi = h;
}

// ---------------------------------------------------------------------------
// fp32 -> (bf16 hi, bf16 lo) split, 4 elems/thread
// ---------------------------------------------------------------------------
__global__ void split4(const float* __restrict__ in,
                       bf16* __restrict__ hi, bf16* __restrict__ lo, int n4) {
    int i = blockIdx.x * blockDim.x + threadIdx.x;
    if (i < n4) {
        float4 v = ((const float4*)in)[i];
        uint32_t h0, l0, h1, l1;
        split_pack(v.x, v.y, h0, l0);
        split_pack(v.z, v.w, h1, l1);
        ((uint2*)hi)[i] = make_uint2(h0, h1);
        ((uint2*)lo)[i] = make_uint2(l0, l1);
    }
}

// fused split of the 4 weight matrices (blockIdx.y selects the weight)
__global__ void split4_w(const float* __restrict__ w0, const float* __restrict__ w1,
                         const float* __restrict__ w2, const float* __restrict__ w3,
                         bf16* __restrict__ hi, bf16* __restrict__ lo) {
    const int NW4 = CC * CC / 4;
    const float* src = (blockIdx.y == 0) ? w0 : (blockIdx.y == 1) ? w1
                     : (blockIdx.y == 2) ? w2 : w3;
    int i = blockIdx.x * blockDim.x + threadIdx.x;
    if (i < NW4) {
        float4 v = ((const float4*)src)[i];
        uint32_t h0, l0, h1, l1;
        split_pack(v.x, v.y, h0, l0);
        split_pack(v.z, v.w, h1, l1);
        int o = blockIdx.y * NW4 + i;
        ((uint2*)hi)[o] = make_uint2(h0, h1);
        ((uint2*)lo)[o] = make_uint2(l0, l1);
    }
}

// ---------------------------------------------------------------------------
// Shared GEMM core: 128x128x32 tiles, 256 threads, cp.async double buffer,
// bf16 3-product split. Accumulates c[4][4][4] for warp tile 64x32.
// ---------------------------------------------------------------------------
#define LDT 40            // smem halfs per tile row (32 + 8 pad)
#define TILE_B 10240      // 128*40*2
#define STAGE_B 40960     // 4 tiles
#define NKT (CC/32)       // 24

struct GemmCore {
    uint32_t sb;
    int tid, lane, wid, wm, wn, m0, n0;
    const bf16 *Ahi, *Alo, *Bhi, *Blo;
    float c[4][4][4];

    __device__ __forceinline__ void load_stage(int kt, int s) {
        const int k0 = kt * 32;
        const uint32_t base = sb + s * STAGE_B;
#pragma unroll
        for (int i = 0; i < 2; i++) {
            int idx = tid + i * 256;
            int r = idx >> 2, c4 = idx & 3;
            size_t gA = (size_t)(m0 + r) * CC + k0 + c4 * 8;
            size_t gB = (size_t)(n0 + r) * CC + k0 + c4 * 8;
            uint32_t so = (uint32_t)(r * LDT + c4 * 8) * 2;
            cp16(base + so,              Ahi + gA);
            cp16(base + TILE_B + so,     Alo + gA);
            cp16(base + 2 * TILE_B + so, Bhi + gB);
            cp16(base + 3 * TILE_B + so, Blo + gB);
        }
        CP_COMMIT();
    }

    __device__ __forceinline__ void run() {
#pragma unroll
        for (int a = 0; a < 4; a++)
#pragma unroll
            for (int bq = 0; bq < 4; bq++)
#pragma unroll
                for (int e = 0; e < 4; e++) c[a][bq][e] = 0.f;

        load_stage(0, 0);
        const int arow = wm * 64 + (lane & 7) + ((lane >> 3) & 1) * 8;
        const int brow = wn * 32 + (lane & 7) + (lane >> 4) * 8;

        for (int kt = 0; kt < NKT; kt++) {
            const int s = kt & 1;
            if (kt + 1 < NKT) { load_stage(kt + 1, s ^ 1); CP_WAIT1(); }
            else              { CP_WAIT0(); }
            __syncthreads();
            const uint32_t base = sb + s * STAGE_B;
#pragma unroll
            for (int k16 = 0; k16 < 2; k16++) {
                uint32_t aHi[4][4], aLo[4][4], bHi[2][4], bLo[2][4];
                const int acol = k16 * 16 + (lane >> 4) * 8;
                const int bcol = k16 * 16 + ((lane >> 3) & 1) * 8;
#pragma unroll
                for (int mi = 0; mi < 4; mi++) {
                    uint32_t ad = base + (uint32_t)((arow + mi * 16) * LDT + acol) * 2;
                    ldsm4(aHi[mi], ad);
                    ldsm4(aLo[mi], ad + TILE_B);
                }
#pragma unroll
                for (int njp = 0; njp < 2; njp++) {
                    uint32_t bd = base + 2 * TILE_B
                                + (uint32_t)((brow + njp * 16) * LDT + bcol) * 2;
                    ldsm4(bHi[njp], bd);
                    ldsm4(bLo[njp], bd + TILE_B);
                }
#pragma unroll
                for (int mi = 0; mi < 4; mi++)
#pragma unroll
                    for (int nj = 0; nj < 4; nj++) {
                        const uint32_t* bh = &bHi[nj >> 1][(nj & 1) * 2];
                        const uint32_t* bl = &bLo[nj >> 1][(nj & 1) * 2];
                        mma16816(c[mi][nj], aHi[mi], bh);
                        mma16816(c[mi][nj], aHi[mi], bl);
                        mma16816(c[mi][nj], aLo[mi], bh);
                    }
            }
            __syncthreads();
        }
    }
};

// ---------------------------------------------------------------------------
// Fused QKV projection: C[M,2304] = X @ [Wq;Wk;Wv]^T, split-bf16 outputs.
// Q segment pre-scaled by D^-0.5 * log2(e).
// ---------------------------------------------------------------------------
__global__ __launch_bounds__(256) void gemm_qkv(
    const bf16* __restrict__ Xhi, const bf16* __restrict__ Xlo,
    const bf16* __restrict__ Whi, const bf16* __restrict__ Wlo,
    bf16* __restrict__ qhi, bf16* __restrict__ qlo,
    bf16* __restrict__ khi, bf16* __restrict__ klo,
    bf16* __restrict__ vhi, bf16* __restrict__ vlo)
{
    extern __shared__ __align__(16) char smem[];
    GemmCore g;
    g.sb = smem_u32(smem);
    g.tid = threadIdx.x; g.lane = g.tid & 31; g.wid = g.tid >> 5;
    g.wm = g.wid >> 2; g.wn = g.wid & 3;
    g.m0 = blockIdx.y * 128; g.n0 = blockIdx.x * 128;
    g.Ahi = Xhi; g.Alo = Xlo; g.Bhi = Whi; g.Blo = Wlo;
    g.run();

    const int seg = g.n0 / CC;            // 0=q, 1=k, 2=v (segments 128-aligned)
    const int nloc = g.n0 - seg * CC;
    bf16 *Dhi, *Dlo;
    float scale;
    if (seg == 0)      { Dhi = qhi; Dlo = qlo; scale = 0.125f * 1.4426950408889634f; }
    else if (seg == 1) { Dhi = khi; Dlo = klo; scale = 1.0f; }
    else               { Dhi = vhi; Dlo = vlo; scale = 1.0f; }

    const int gr = g.lane >> 2, q2 = (g.lane & 3) * 2;
#pragma unroll
    for (int mi = 0; mi < 4; mi++)
#pragma unroll
        for (int nj = 0; nj < 4; nj++) {
            int row = g.m0 + g.wm * 64 + mi * 16 + gr;
            int col = nloc + g.wn * 32 + nj * 8 + q2;
            uint32_t ph, pl;
            split_pack(g.c[mi][nj][0] * scale, g.c[mi][nj][1] * scale, ph, pl);
            *(uint32_t*)&Dhi[(size_t)row * CC + col] = ph;
            *(uint32_t*)&Dlo[(size_t)row * CC + col] = pl;
            split_pack(g.c[mi][nj][2] * scale, g.c[mi][nj][3] * scale, ph, pl);
            *(uint32_t*)&Dhi[(size_t)(row + 8) * CC + col] = ph;
            *(uint32_t*)&Dlo[(size_t)(row + 8) * CC + col] = pl;
        }
}

// ---------------------------------------------------------------------------
// Output projection: out[M,768] = O @ Wp^T, fp32 output.
// ---------------------------------------------------------------------------
__global__ __launch_bounds__(256) void gemm_proj(
    const bf16* __restrict__ Ahi, const bf16* __restrict__ Alo,
    const bf16* __restrict__ Bhi, const bf16* __restrict__ Blo,
    float* __restrict__ Cf)
{
    extern __shared__ __align__(16) char smem[];
    GemmCore g;
    g.sb = smem_u32(smem);
    g.tid = threadIdx.x; g.lane = g.tid & 31; g.wid = g.tid >> 5;
    g.wm = g.wid >> 2; g.wn = g.wid & 3;
    g.m0 = blockIdx.y * 128; g.n0 = blockIdx.x * 128;
    g.Ahi = Ahi; g.Alo = Alo; g.Bhi = Bhi; g.Blo = Blo;
    g.run();

    const int gr = g.lane >> 2, q2 = (g.lane & 3) * 2;
#pragma unroll
    for (int mi = 0; mi < 4; mi++)
#pragma unroll
        for (int nj = 0; nj < 4; nj++) {
            int row = g.m0 + g.wm * 64 + mi * 16 + gr;
            int col = g.n0 + g.wn * 32 + nj * 8 + q2;
            *(float2*)&Cf[(size_t)row * CC + col] =
                make_float2(g.c[mi][nj][0], g.c[mi][nj][1]);
            *(float2*)&Cf[(size_t)(row + 8) * CC + col] =
                make_float2(g.c[mi][nj][2], g.c[mi][nj][3]);
        }
}

// ---------------------------------------------------------------------------
// Causal flash attention on mma.sync, bf16 3-product splits, exp2 softmax.
// Block: 128 q-rows x head, 256 threads (8 warps x 16 rows).
// ---------------------------------------------------------------------------
#define QTILE_B 18432      // 128*72*2
#define ATN_TILE_B 9216    // 64*72*2
#define ATN_STG_B  36864   // 4 tiles (K hi/lo, V hi/lo)

__global__ __launch_bounds__(256) void attn_mma(
    const bf16* __restrict__ Qhi, const bf16* __restrict__ Qlo,
    const bf16* __restrict__ Khi, const bf16* __restrict__ Klo,
    const bf16* __restrict__ Vhi, const bf16* __restrict__ Vlo,
    bf16* __restrict__ Ohi, bf16* __restrict__ Olo)
{
    extern __shared__ __align__(16) char smem[];
    const uint32_t sb = smem_u32(smem);
    const int tid = threadIdx.x, lane = tid & 31, wid = tid >> 5;
    const int bh = blockIdx.y, b = bh / HH, h = bh - b * HH;
    const int qt = (int)gridDim.x - 1 - (int)blockIdx.x;  // heavy first
    const int q0 = qt * 128;
    const int nkt = 2 * qt + 2;
    const int wq0 = wid * 16;
    const uint32_t oQlo = QTILE_B, oStg = 2 * QTILE_B;

    // --- Q tiles (hi/lo) into smem ---
    {
        const bf16* qh = Qhi + (size_t)(b * TT + q0) * CC + h * DD;
        const bf16* ql = Qlo + (size_t)(b * TT + q0) * CC + h * DD;
#pragma unroll
        for (int i = 0; i < 4; i++) {
            int idx = tid + i * 256;
            int r = idx >> 3, c8 = idx & 7;
            uint32_t so = (uint32_t)(r * 72 + c8 * 8) * 2;
            *(uint4*)(smem + so)        = *(const uint4*)(qh + (size_t)r * CC + c8 * 8);
            *(uint4*)(smem + oQlo + so) = *(const uint4*)(ql + (size_t)r * CC + c8 * 8);
        }
    }

    auto load_kv = [&](int kt, int s) {
        const uint32_t base = sb + oStg + s * ATN_STG_B;
        const size_t rb = (size_t)(b * TT + kt * 64) * CC + h * DD;
#pragma unroll
        for (int i = 0; i < 2; i++) {
            int idx = tid + i * 256;
            int r = idx >> 3, c8 = idx & 7;
            uint32_t so = (uint32_t)(r * 72 + c8 * 8) * 2;
            size_t go = rb + (size_t)r * CC + c8 * 8;
            cp16(base + so,                  Khi + go);
            cp16(base + ATN_TILE_B + so,     Klo + go);
            cp16(base + 2 * ATN_TILE_B + so, Vhi + go);
            cp16(base + 3 * ATN_TILE_B + so, Vlo + go);
        }
        CP_COMMIT();
    };

    load_kv(0, 0);
    __syncthreads();

    // --- Q fragments (fixed for the whole block) ---
    uint32_t qa_hi[4][4], qa_lo[4][4];
    {
        const int ar = wq0 + (lane & 7) + ((lane >> 3) & 1) * 8;
#pragma unroll
        for (int kk = 0; kk < 4; kk++) {
            const int ac = kk * 16 + (lane >> 4) * 8;
            uint32_t ad = sb + (uint32_t)(ar * 72 + ac) * 2;
            ldsm4(qa_hi[kk], ad);
            ldsm4(qa_lo[kk], ad + oQlo);
        }
    }

    float o[8][4] = {};
    float mr0 = -1e30f, mr1 = -1e30f, lr0 = 0.f, lr1 = 0.f;
    const int g = lane >> 2, q2 = (lane & 3) * 2;

    for (int kt = 0; kt < nkt; kt++) {
        const int s = kt & 1;
        if (kt + 1 < nkt) { load_kv(kt + 1, s ^ 1); CP_WAIT1(); }
        else              { CP_WAIT0(); }
        __syncthreads();
        const uint32_t base = sb + oStg + s * ATN_STG_B;

        // --- S = Q K^T (pre-scaled by 0.125*log2e via Q) ---
        float cs[8][4] = {};
        {
            const int kr = (lane & 7) + (lane >> 4) * 8;
#pragma unroll
            for (int njp = 0; njp < 4; njp++)
#pragma unroll
                for (int kk = 0; kk < 4; kk++) {
                    const int kc = kk * 16 + ((lane >> 3) & 1) * 8;
                    uint32_t kd = base + (uint32_t)((kr + njp * 16) * 72 + kc) * 2;
                    uint32_t kb_hi[4], kb_lo[4];
                    ldsm4(kb_hi, kd);
                    ldsm4(kb_lo, kd + ATN_TILE_B);
#pragma unroll
                    for (int j = 0; j < 2; j++) {
                        mma16816(cs[njp * 2 + j], qa_hi[kk], &kb_hi[j * 2]);
                        mma16816(cs[njp * 2 + j], qa_hi[kk], &kb_lo[j * 2]);
                        mma16816(cs[njp * 2 + j], qa_lo[kk], &kb_hi[j * 2]);
                    }
                }
        }

        // --- causal mask (last two k-tiles only) ---
        if (kt >= 2 * qt) {
            const int k0g = kt * 64;
            const int qrg = q0 + wq0 + g;
#pragma unroll
            for (int nj = 0; nj < 8; nj++)
#pragma unroll
                for (int e = 0; e < 4; e++) {
                    int qr = qrg + ((e >> 1) << 3);
                    int kc = k0g + nj * 8 + q2 + (e & 1);
                    if (kc > qr) cs[nj][e] = -1e30f;
                }
        }

        // --- online softmax (base-2) ---
        float mx0 = -1e30f, mx1 = -1e30f;
#pragma unroll
        for (int nj = 0; nj < 8; nj++) {
            mx0 = fmaxf(mx0, fmaxf(cs[nj][0], cs[nj][1]));
            mx1 = fmaxf(mx1, fmaxf(cs[nj][2], cs[nj][3]));
        }
        mx0 = fmaxf(mx0, __shfl_xor_sync(0xffffffffu, mx0, 1));
        mx0 = fmaxf(mx0, __shfl_xor_sync(0xffffffffu, mx0, 2));
        mx1 = fmaxf(mx1, __shfl_xor_sync(0xffffffffu, mx1, 1));
        mx1 = fmaxf(mx1, __shfl_xor_sync(0xffffffffu, mx1, 2));
        float mn0 = fmaxf(mr0, mx0), mn1 = fmaxf(mr1, mx1);
        float al0 = ex2(mr0 - mn0), al1 = ex2(mr1 - mn1);
        mr0 = mn0; mr1 = mn1;

        float s0 = 0.f, s1 = 0.f;
#pragma unroll
        for (int nj = 0; nj < 8; nj++) {
            cs[nj][0] = ex2(cs[nj][0] - mn0);
            cs[nj][1] = ex2(cs[nj][1] - mn0);
            cs[nj][2] = ex2(cs[nj][2] - mn1);
            cs[nj][3] = ex2(cs[nj][3] - mn1);
            s0 += cs[nj][0] + cs[nj][1];
            s1 += cs[nj][2] + cs[nj][3];
        }
        s0 += __shfl_xor_sync(0xffffffffu, s0, 1);
        s0 += __shfl_xor_sync(0xffffffffu, s0, 2);
        s1 += __shfl_xor_sync(0xffffffffu, s1, 1);
        s1 += __shfl_xor_sync(0xffffffffu, s1, 2);
        lr0 = lr0 * al0 + s0;
        lr1 = lr1 * al1 + s1;
#pragma unroll
        for (int dj = 0; dj < 8; dj++) {
            o[dj][0] *= al0; o[dj][1] *= al0;
            o[dj][2] *= al1; o[dj][3] *= al1;
        }

        // --- split P into bf16 hi/lo A-fragments (register-only) ---
        uint32_t pa_hi[4][4], pa_lo[4][4];
#pragma unroll
        for (int kk2 = 0; kk2 < 4; kk2++) {
            split_pack(cs[2 * kk2][0],     cs[2 * kk2][1],     pa_hi[kk2][0], pa_lo[kk2][0]);
            split_pack(cs[2 * kk2][2],     cs[2 * kk2][3],     pa_hi[kk2][1], pa_lo[kk2][1]);
            split_pack(cs[2 * kk2 + 1][0], cs[2 * kk2 + 1][1], pa_hi[kk2][2], pa_lo[kk2][2]);
            split_pack(cs[2 * kk2 + 1][2], cs[2 * kk2 + 1][3], pa_hi[kk2][3], pa_lo[kk2][3]);
        }

        // --- O += P V (V via ldmatrix.trans) ---
        {
            const int vr = (lane & 7) + ((lane >> 3) & 1) * 8;
#pragma unroll
            for (int djp = 0; djp < 4; djp++)
#pragma unroll
                for (int kk2 = 0; kk2 < 4; kk2++) {
                    const int vc = djp * 16 + (lane >> 4) * 8;
                    uint32_t vd = base + 2 * ATN_TILE_B
                                + (uint32_t)((vr + kk2 * 16) * 72 + vc) * 2;
                    uint32_t vb_hi[4], vb_lo[4];
                    ldsm4t(vb_hi, vd);
                    ldsm4t(vb_lo, vd + ATN_TILE_B);
#pragma unroll
                    for (int j = 0; j < 2; j++) {
                        mma16816(o[djp * 2 + j], pa_hi[kk2], &vb_hi[j * 2]);
                        mma16816(o[djp * 2 + j], pa_hi[kk2], &vb_lo[j * 2]);
                        mma16816(o[djp * 2 + j], pa_lo[kk2], &vb_hi[j * 2]);
                    }
                }
        }
        __syncthreads();
    }

    // --- epilogue: normalize, split to bf16 hi/lo, store ---
    float inv0 = 1.f / lr0, inv1 = 1.f / lr1;
    const size_t r0 = (size_t)(b * TT + q0 + wq0 + g) * CC + h * DD;
    const size_t r1 = r0 + (size_t)8 * CC;
#pragma unroll
    for (int dj = 0; dj < 8; dj++) {
        int col = dj * 8 + q2;
        uint32_t ph, pl;
        split_pack(o[dj][0] * inv0, o[dj][1] * inv0, ph, pl);
        *(uint32_t*)&Ohi[r0 + col] = ph;
        *(uint32_t*)&Olo[r0 + col] = pl;
        split_pack(o[dj][2] * inv1, o[dj][3] * inv1, ph, pl);
        *(uint32_t*)&Ohi[r1 + col] = ph;
        *(uint32_t*)&Olo[r1 + col] = pl;
    }
}

// ---------------------------------------------------------------------------
extern "C" void kernel_launch(void* const* d_in, const int* in_sizes, int n_in,
                              void* d_out, int out_size) {
    const float* x  = (const float*)d_in[0];
    const float* Wq = (const float*)d_in[1];
    const float* Wk = (const float*)d_in[2];
    const float* Wv = (const float*)d_in[3];
    const float* Wp = (const float*)d_in[4];
    float* out = (float*)d_out;

    bf16 *xhi, *xlo, *whi, *wlo, *qhi, *qlo, *khi, *klo, *vhi, *vlo, *ohi, *olo;
    cudaGetSymbolAddress((void**)&xhi, g_xhi);
    cudaGetSymbolAddress((void**)&xlo, g_xlo);
    cudaGetSymbolAddress((void**)&whi, g_whi);
    cudaGetSymbolAddress((void**)&wlo, g_wlo);
    cudaGetSymbolAddress((void**)&qhi, g_qhi);
    cudaGetSymbolAddress((void**)&qlo, g_qlo);
    cudaGetSymbolAddress((void**)&khi, g_khi);
    cudaGetSymbolAddress((void**)&klo, g_klo);
    cudaGetSymbolAddress((void**)&vhi, g_vhi);
    cudaGetSymbolAddress((void**)&vlo, g_vlo);
    cudaGetSymbolAddress((void**)&ohi, g_ohi);
    cudaGetSymbolAddress((void**)&olo, g_olo);

    cudaFuncSetAttribute(gemm_qkv,
                         cudaFuncAttributeMaxDynamicSharedMemorySize, 2 * STAGE_B);
    cudaFuncSetAttribute(gemm_proj,
                         cudaFuncAttributeMaxDynamicSharedMemorySize, 2 * STAGE_B);
    const int smem_attn = 2 * QTILE_B + 2 * ATN_STG_B;  // 110592
    cudaFuncSetAttribute(attn_mma,
                         cudaFuncAttributeMaxDynamicSharedMemorySize, smem_attn);

    const int NX4 = MM * CC / 4, NW4 = CC * CC / 4;
    split4<<<(NX4 + 255) / 256, 256>>>(x, xhi, xlo, NX4);
    split4_w<<<dim3((NW4 + 255) / 256, 4), 256>>>(Wq, Wk, Wv, Wp, whi, wlo);

    // fused QKV projection: N = 2304
    gemm_qkv<<<dim3(3 * CC / 128, MM / 128), 256, 2 * STAGE_B>>>(
        xhi, xlo, whi, wlo, qhi, qlo, khi, klo, vhi, vlo);

    attn_mma<<<dim3(TT / 128, BB * HH), 256, smem_attn>>>(qhi, qlo, khi, klo,
                                                          vhi, vlo, ohi, olo);

    gemm_proj<<<dim3(CC / 128, MM / 128), 256, 2 * STAGE_B>>>(
        ohi, olo, whi + 3 * CC * CC, wlo + 3 * CC * CC, out);
}